// round 1
// baseline (speedup 1.0000x reference)
#include <cuda_runtime.h>
#include <math.h>

// SlowMAF: 31 stacked per-dim MLPs (32 -> 24 -> 24 -> 24 -> 2, LeakyReLU 0.2),
// z[:, 31-i] = x[:,i]*exp(s_i)+t_i, log_det = sum_i s_i.
// Inputs (metadata order): x, p0, W1, b1, W2, b2, W3, b3, W4, b4
// Output: [ z (B*32 f32), log_det (B f32) ]

#define NHID 24
#define THREADS 128
#define ROWS_PER_CTA 256   // THREADS * R
#define XPITCH 33          // pad to kill 32-way bank conflicts

__global__ void slowmaf_init_kernel(const float* __restrict__ x,
                                    const float* __restrict__ p0,
                                    float* __restrict__ z,
                                    float* __restrict__ ld, int B) {
    int row = blockIdx.x * blockDim.x + threadIdx.x;
    if (row < B) {
        float s0 = p0[0], t0 = p0[1];
        // order[0] = 31 (parity=False): z[:,31] = x[:,0]*exp(p0[0]) + p0[1]
        z[row * 32 + 31] = x[row * 32 + 0] * expf(s0) + t0;
        ld[row] = s0;
    }
}

__global__ __launch_bounds__(THREADS, 3) void slowmaf_main_kernel(
    const float* __restrict__ x,
    const float* __restrict__ W1, const float* __restrict__ b1,
    const float* __restrict__ W2, const float* __restrict__ b2,
    const float* __restrict__ W3, const float* __restrict__ b3,
    const float* __restrict__ W4, const float* __restrict__ b4,
    float* __restrict__ z, float* __restrict__ ld)
{
    __shared__ float xs[ROWS_PER_CTA * XPITCH];
    __shared__ float w1t[32 * NHID];       // [j][o]
    __shared__ float w2t[NHID * NHID];     // [hin][o]
    __shared__ float w3t[NHID * NHID];     // [hin][o]
    __shared__ float w4t[NHID * 2];        // [hin][o]
    __shared__ float b1s[NHID], b2s[NHID], b3s[NHID], b4s[2];

    const int k    = blockIdx.y;                 // 0..30  (torch layer i = k+1)
    const int tile = blockIdx.x * ROWS_PER_CTA;
    const int tid  = threadIdx.x;

    // --- stage x tile (coalesced) ---
    #pragma unroll 4
    for (int idx = tid; idx < ROWS_PER_CTA * 32; idx += THREADS) {
        int r = idx >> 5, c = idx & 31;
        xs[r * XPITCH + c] = x[(tile + r) * 32 + c];
    }
    // --- stage weights (transposed so inner o-loop reads contiguous smem) ---
    for (int idx = tid; idx < 32 * NHID; idx += THREADS) {
        int j = idx / NHID, o = idx % NHID;
        w1t[idx] = W1[k * (NHID * 32) + o * 32 + j];
    }
    for (int idx = tid; idx < NHID * NHID; idx += THREADS) {
        int hin = idx / NHID, o = idx % NHID;
        w2t[idx] = W2[k * (NHID * NHID) + o * NHID + hin];
        w3t[idx] = W3[k * (NHID * NHID) + o * NHID + hin];
    }
    if (tid < NHID * 2) {
        int hin = tid >> 1, o = tid & 1;
        w4t[tid] = W4[k * (2 * NHID) + o * NHID + hin];
    }
    if (tid < NHID) {
        b1s[tid] = b1[k * NHID + tid];
        b2s[tid] = b2[k * NHID + tid];
        b3s[tid] = b3[k * NHID + tid];
    }
    if (tid < 2) b4s[tid] = b4[k * 2 + tid];
    __syncthreads();

    // Each thread: 2 rows (register blocking amortizes the weight LDS).
    float a0[NHID], a1[NHID], h0[NHID], h1[NHID];
    const float* x0p = &xs[tid * XPITCH];
    const float* x1p = &xs[(tid + THREADS) * XPITCH];

    // ---- layer 1 (causal: only columns 0..k are nonzero) ----
    #pragma unroll
    for (int o = 0; o < NHID; o++) { a0[o] = b1s[o]; a1[o] = b1s[o]; }
    #pragma unroll 1
    for (int j = 0; j <= k; j++) {
        float xv0 = x0p[j];
        float xv1 = x1p[j];
        const float* wp = &w1t[j * NHID];
        #pragma unroll
        for (int o = 0; o < NHID; o++) {
            float w = wp[o];
            a0[o] = fmaf(w, xv0, a0[o]);
            a1[o] = fmaf(w, xv1, a1[o]);
        }
    }
    #pragma unroll
    for (int o = 0; o < NHID; o++) {
        h0[o] = fmaxf(a0[o], 0.2f * a0[o]);   // LeakyReLU(0.2)
        h1[o] = fmaxf(a1[o], 0.2f * a1[o]);
    }

    // ---- layer 2 ----
    #pragma unroll
    for (int o = 0; o < NHID; o++) { a0[o] = b2s[o]; a1[o] = b2s[o]; }
    #pragma unroll
    for (int hin = 0; hin < NHID; hin++) {
        float v0 = h0[hin], v1 = h1[hin];
        const float* wp = &w2t[hin * NHID];
        #pragma unroll
        for (int o = 0; o < NHID; o++) {
            float w = wp[o];
            a0[o] = fmaf(w, v0, a0[o]);
            a1[o] = fmaf(w, v1, a1[o]);
        }
    }
    #pragma unroll
    for (int o = 0; o < NHID; o++) {
        h0[o] = fmaxf(a0[o], 0.2f * a0[o]);
        h1[o] = fmaxf(a1[o], 0.2f * a1[o]);
    }

    // ---- layer 3 ----
    #pragma unroll
    for (int o = 0; o < NHID; o++) { a0[o] = b3s[o]; a1[o] = b3s[o]; }
    #pragma unroll
    for (int hin = 0; hin < NHID; hin++) {
        float v0 = h0[hin], v1 = h1[hin];
        const float* wp = &w3t[hin * NHID];
        #pragma unroll
        for (int o = 0; o < NHID; o++) {
            float w = wp[o];
            a0[o] = fmaf(w, v0, a0[o]);
            a1[o] = fmaf(w, v1, a1[o]);
        }
    }
    #pragma unroll
    for (int o = 0; o < NHID; o++) {
        h0[o] = fmaxf(a0[o], 0.2f * a0[o]);
        h1[o] = fmaxf(a1[o], 0.2f * a1[o]);
    }

    // ---- layer 4: (s, t) ----
    float s0 = b4s[0], t0 = b4s[1];
    float s1 = b4s[0], t1 = b4s[1];
    #pragma unroll
    for (int hin = 0; hin < NHID; hin++) {
        float ws = w4t[hin * 2 + 0];
        float wt = w4t[hin * 2 + 1];
        s0 = fmaf(ws, h0[hin], s0);
        t0 = fmaf(wt, h0[hin], t0);
        s1 = fmaf(ws, h1[hin], s1);
        t1 = fmaf(wt, h1[hin], t1);
    }

    // ---- epilogue: z[:, 31-(k+1)] = x[:,k+1]*exp(s)+t ; logdet += s ----
    const int col  = 30 - k;
    const int row0 = tile + tid;
    const int row1 = row0 + THREADS;
    float xk0 = x0p[k + 1];
    float xk1 = x1p[k + 1];
    z[row0 * 32 + col] = xk0 * expf(s0) + t0;
    z[row1 * 32 + col] = xk1 * expf(s1) + t1;
    atomicAdd(&ld[row0], s0);
    atomicAdd(&ld[row1], s1);
}

extern "C" void kernel_launch(void* const* d_in, const int* in_sizes, int n_in,
                              void* d_out, int out_size) {
    const float* x  = (const float*)d_in[0];
    const float* p0 = (const float*)d_in[1];
    const float* W1 = (const float*)d_in[2];
    const float* b1 = (const float*)d_in[3];
    const float* W2 = (const float*)d_in[4];
    const float* b2 = (const float*)d_in[5];
    const float* W3 = (const float*)d_in[6];
    const float* b3 = (const float*)d_in[7];
    const float* W4 = (const float*)d_in[8];
    const float* b4 = (const float*)d_in[9];

    const int B = in_sizes[0] / 32;          // 65536
    float* z  = (float*)d_out;               // B*32
    float* ld = z + (size_t)B * 32;          // B

    slowmaf_init_kernel<<<(B + 255) / 256, 256>>>(x, p0, z, ld, B);

    dim3 grid(B / ROWS_PER_CTA, 31);
    slowmaf_main_kernel<<<grid, THREADS>>>(x, W1, b1, W2, b2, W3, b3, W4, b4, z, ld);
}

// round 2
// speedup vs baseline: 1.1485x; 1.1485x over previous
#include <cuda_runtime.h>
#include <math.h>

// SlowMAF: 31 stacked per-dim MLPs (32 -> 24 -> 24 -> 24 -> 2, LeakyReLU 0.2),
// z[:, 31-i] = x[:,i]*exp(s_i)+t_i, log_det = sum_i s_i.
// Packed fp32x2 version: output-neuron pairs packed into f32x2 lanes.
// Inputs (metadata order): x, p0, W1, b1, W2, b2, W3, b3, W4, b4
// Output: [ z (B*32 f32), log_det (B f32) ]

#define NHID 24
#define NP   (NHID / 2)      // 12 packed pairs
#define THREADS 128
#define ROWS_PER_CTA 256     // THREADS * 2 rows/thread
#define XPITCH 33            // pad to kill bank conflicts

typedef unsigned long long u64;

__device__ __forceinline__ u64 pack2(float lo, float hi) {
    u64 r; asm("mov.b64 %0, {%1, %2};" : "=l"(r) : "f"(lo), "f"(hi)); return r;
}
__device__ __forceinline__ void unpack2(float& lo, float& hi, u64 v) {
    asm("mov.b64 {%0, %1}, %2;" : "=f"(lo), "=f"(hi) : "l"(v));
}
__device__ __forceinline__ u64 fma2(u64 a, u64 b, u64 c) {
    u64 d; asm("fma.rn.f32x2 %0, %1, %2, %3;" : "=l"(d) : "l"(a), "l"(b), "l"(c)); return d;
}
__device__ __forceinline__ u64 mul2(u64 a, u64 b) {
    u64 d; asm("mul.rn.f32x2 %0, %1, %2;" : "=l"(d) : "l"(a), "l"(b)); return d;
}
// lrelu(a) = max(a, 0.2a) = 0.6a + 0.4|a|, applied lanewise while packed.
__device__ __forceinline__ u64 lrelu2(u64 a) {
    const u64 C06 = 0x3F19999A3F19999Aull;  // {0.6f, 0.6f}
    const u64 C04 = 0x3ECCCCCD3ECCCCCDull;  // {0.4f, 0.4f}
    u64 absa = a & 0x7FFFFFFF7FFFFFFFull;
    return fma2(absa, C04, mul2(a, C06));
}

__global__ void slowmaf_init_kernel(const float* __restrict__ x,
                                    const float* __restrict__ p0,
                                    float* __restrict__ z,
                                    float* __restrict__ ld, int B) {
    int row = blockIdx.x * blockDim.x + threadIdx.x;
    if (row < B) {
        float s0 = p0[0], t0 = p0[1];
        z[row * 32 + 31] = x[row * 32 + 0] * expf(s0) + t0;  // order[0] = 31
        ld[row] = s0;
    }
}

__global__ __launch_bounds__(THREADS, 4) void slowmaf_main_kernel(
    const float* __restrict__ x,
    const float* __restrict__ W1, const float* __restrict__ b1,
    const float* __restrict__ W2, const float* __restrict__ b2,
    const float* __restrict__ W3, const float* __restrict__ b3,
    const float* __restrict__ W4, const float* __restrict__ b4,
    float* __restrict__ z, float* __restrict__ ld)
{
    __shared__ float xs[ROWS_PER_CTA * XPITCH];
    __shared__ __align__(16) float w1t[32 * NHID];     // [j][o], o-pairs contiguous
    __shared__ __align__(16) float w2t[NHID * NHID];   // [hin][o]
    __shared__ __align__(16) float w3t[NHID * NHID];   // [hin][o]
    __shared__ __align__(16) float w4t[NHID * 2];      // [hin][{s,t}]
    __shared__ __align__(16) float b1s[NHID], b2s[NHID], b3s[NHID], b4s[2];

    const int k    = blockIdx.y;               // 0..30 (torch layer i = k+1)
    const int tile = blockIdx.x * ROWS_PER_CTA;
    const int tid  = threadIdx.x;

    // --- stage x tile (coalesced) ---
    #pragma unroll 4
    for (int idx = tid; idx < ROWS_PER_CTA * 32; idx += THREADS) {
        int r = idx >> 5, c = idx & 31;
        xs[r * XPITCH + c] = x[(tile + r) * 32 + c];
    }
    // --- stage weights transposed: inner o index contiguous => packed pairs ---
    for (int idx = tid; idx < 32 * NHID; idx += THREADS) {
        int j = idx / NHID, o = idx % NHID;
        w1t[idx] = W1[k * (NHID * 32) + o * 32 + j];
    }
    for (int idx = tid; idx < NHID * NHID; idx += THREADS) {
        int hin = idx / NHID, o = idx % NHID;
        w2t[idx] = W2[k * (NHID * NHID) + o * NHID + hin];
        w3t[idx] = W3[k * (NHID * NHID) + o * NHID + hin];
    }
    if (tid < NHID * 2) {
        int hin = tid >> 1, o = tid & 1;
        w4t[tid] = W4[k * (2 * NHID) + o * NHID + hin];
    }
    if (tid < NHID) {
        b1s[tid] = b1[k * NHID + tid];
        b2s[tid] = b2[k * NHID + tid];
        b3s[tid] = b3[k * NHID + tid];
    }
    if (tid < 2) b4s[tid] = b4[k * 2 + tid];
    __syncthreads();

    // Two rows per thread, 12 packed (o,o+1) accumulators per row.
    u64 A0[NP], A1[NP], H0[NP], H1[NP];
    const float* x0p = &xs[tid * XPITCH];
    const float* x1p = &xs[(tid + THREADS) * XPITCH];

    const u64* b1p = (const u64*)b1s;
    const u64* b2p = (const u64*)b2s;
    const u64* b3p = (const u64*)b3s;

    // ---- layer 1 (causal: columns 0..k) ----
    #pragma unroll
    for (int o = 0; o < NP; o++) { A0[o] = b1p[o]; A1[o] = b1p[o]; }
    for (int j = 0; j <= k; j++) {
        u64 v0 = pack2(x0p[j], x0p[j]);
        u64 v1 = pack2(x1p[j], x1p[j]);
        const u64* wp = (const u64*)&w1t[j * NHID];
        #pragma unroll
        for (int o = 0; o < NP; o++) {
            u64 w = wp[o];
            A0[o] = fma2(w, v0, A0[o]);
            A1[o] = fma2(w, v1, A1[o]);
        }
    }
    #pragma unroll
    for (int o = 0; o < NP; o++) { H0[o] = lrelu2(A0[o]); H1[o] = lrelu2(A1[o]); }

    // ---- layer 2 ----
    #pragma unroll
    for (int o = 0; o < NP; o++) { A0[o] = b2p[o]; A1[o] = b2p[o]; }
    #pragma unroll
    for (int hp = 0; hp < NP; hp++) {
        float h0lo, h0hi, h1lo, h1hi;
        unpack2(h0lo, h0hi, H0[hp]);
        unpack2(h1lo, h1hi, H1[hp]);
        const u64* wpa = (const u64*)&w2t[(2 * hp) * NHID];
        const u64* wpb = (const u64*)&w2t[(2 * hp + 1) * NHID];
        u64 va0 = pack2(h0lo, h0lo), vb0 = pack2(h0hi, h0hi);
        u64 va1 = pack2(h1lo, h1lo), vb1 = pack2(h1hi, h1hi);
        #pragma unroll
        for (int o = 0; o < NP; o++) {
            u64 wa = wpa[o], wb = wpb[o];
            A0[o] = fma2(wa, va0, A0[o]);
            A1[o] = fma2(wa, va1, A1[o]);
            A0[o] = fma2(wb, vb0, A0[o]);
            A1[o] = fma2(wb, vb1, A1[o]);
        }
    }
    #pragma unroll
    for (int o = 0; o < NP; o++) { H0[o] = lrelu2(A0[o]); H1[o] = lrelu2(A1[o]); }

    // ---- layer 3 ----
    #pragma unroll
    for (int o = 0; o < NP; o++) { A0[o] = b3p[o]; A1[o] = b3p[o]; }
    #pragma unroll
    for (int hp = 0; hp < NP; hp++) {
        float h0lo, h0hi, h1lo, h1hi;
        unpack2(h0lo, h0hi, H0[hp]);
        unpack2(h1lo, h1hi, H1[hp]);
        const u64* wpa = (const u64*)&w3t[(2 * hp) * NHID];
        const u64* wpb = (const u64*)&w3t[(2 * hp + 1) * NHID];
        u64 va0 = pack2(h0lo, h0lo), vb0 = pack2(h0hi, h0hi);
        u64 va1 = pack2(h1lo, h1lo), vb1 = pack2(h1hi, h1hi);
        #pragma unroll
        for (int o = 0; o < NP; o++) {
            u64 wa = wpa[o], wb = wpb[o];
            A0[o] = fma2(wa, va0, A0[o]);
            A1[o] = fma2(wa, va1, A1[o]);
            A0[o] = fma2(wb, vb0, A0[o]);
            A1[o] = fma2(wb, vb1, A1[o]);
        }
    }
    #pragma unroll
    for (int o = 0; o < NP; o++) { H0[o] = lrelu2(A0[o]); H1[o] = lrelu2(A1[o]); }

    // ---- layer 4: packed (s, t) ----
    const u64* w4p = (const u64*)w4t;          // pair hin -> {ws, wt}
    u64 st0 = *(const u64*)b4s;
    u64 st1 = st0;
    #pragma unroll
    for (int hp = 0; hp < NP; hp++) {
        float h0lo, h0hi, h1lo, h1hi;
        unpack2(h0lo, h0hi, H0[hp]);
        unpack2(h1lo, h1hi, H1[hp]);
        u64 wa = w4p[2 * hp], wb = w4p[2 * hp + 1];
        st0 = fma2(wa, pack2(h0lo, h0lo), st0);
        st0 = fma2(wb, pack2(h0hi, h0hi), st0);
        st1 = fma2(wa, pack2(h1lo, h1lo), st1);
        st1 = fma2(wb, pack2(h1hi, h1hi), st1);
    }

    // ---- epilogue: z[:, 30-k] = x[:,k+1]*exp(s)+t ; logdet += s ----
    float s0, t0, s1, t1;
    unpack2(s0, t0, st0);
    unpack2(s1, t1, st1);
    const int col  = 30 - k;
    const int row0 = tile + tid;
    const int row1 = row0 + THREADS;
    z[row0 * 32 + col] = x0p[k + 1] * expf(s0) + t0;
    z[row1 * 32 + col] = x1p[k + 1] * expf(s1) + t1;
    atomicAdd(&ld[row0], s0);
    atomicAdd(&ld[row1], s1);
}

extern "C" void kernel_launch(void* const* d_in, const int* in_sizes, int n_in,
                              void* d_out, int out_size) {
    const float* x  = (const float*)d_in[0];
    const float* p0 = (const float*)d_in[1];
    const float* W1 = (const float*)d_in[2];
    const float* b1 = (const float*)d_in[3];
    const float* W2 = (const float*)d_in[4];
    const float* b2 = (const float*)d_in[5];
    const float* W3 = (const float*)d_in[6];
    const float* b3 = (const float*)d_in[7];
    const float* W4 = (const float*)d_in[8];
    const float* b4 = (const float*)d_in[9];

    const int B = in_sizes[0] / 32;          // 65536
    float* z  = (float*)d_out;               // B*32
    float* ld = z + (size_t)B * 32;          // B

    slowmaf_init_kernel<<<(B + 255) / 256, 256>>>(x, p0, z, ld, B);

    dim3 grid(B / ROWS_PER_CTA, 31);
    slowmaf_main_kernel<<<grid, THREADS>>>(x, W1, b1, W2, b2, W3, b3, W4, b4, z, ld);
}